// round 7
// baseline (speedup 1.0000x reference)
#include <cuda_runtime.h>

// Accumulators in __device__ globals (allocation-free scratch). They are
// read AND reset by the last block each launch, so state is invariant
// across graph replays (zero-init at module load covers the first call).
__device__ double g_inter = 0.0;        // sum(actual * desire)
__device__ double g_desire_sum = 0.0;   // sum(desire)
__device__ unsigned long long g_count = 0ull;  // sum(actual), exact integer
__device__ unsigned int g_ticket = 0u;

#define UNROLL 4

// Warp-per-row: 32 lanes x float4 = 128 floats = one row. Each warp owns a
// contiguous chunk of rows (desire loads become L1-sector-friendly).
// occupancy capped at 4 blocks/SM -> 64 regs/thread so all 8 LDG.128 of the
// unrolled body stay in flight (MLP=8/thread).
__global__ __launch_bounds__(256, 4)
void fra_fused_kernel(const float4* __restrict__ o1,
                      const float4* __restrict__ o2,
                      const float*  __restrict__ desire,
                      float* __restrict__ out,
                      int n_rows) {
    const int lane          = threadIdx.x & 31;
    const int warp_in_block = threadIdx.x >> 5;
    const int warps_per_blk = blockDim.x >> 5;
    const int warp_global   = blockIdx.x * warps_per_blk + warp_in_block;
    const int total_warps   = gridDim.x * warps_per_blk;

    // Contiguous chunk of rows per warp.
    const int chunk = (n_rows + total_warps - 1) / total_warps;
    const int row0  = warp_global * chunk;
    const int row1  = (row0 + chunk < n_rows) ? (row0 + chunk) : n_rows;

    double       l_inter = 0.0;
    double       l_des   = 0.0;
    unsigned int l_cnt   = 0u;

    const float margin_sq = 0.390625f;  // (1.25/2)^2

    int row = row0;
    // Main unrolled loop: 8 independent LDG.128 per thread before any use.
    for (; row + UNROLL <= row1; row += UNROLL) {
        float4 a[UNROLL], b[UNROLL];
        #pragma unroll
        for (int u = 0; u < UNROLL; u++) {
            const long base = (long)(row + u) * 32 + lane;
            a[u] = __ldcs(o1 + base);
            b[u] = __ldcs(o2 + base);
        }
        float s[UNROLL];
        #pragma unroll
        for (int u = 0; u < UNROLL; u++) {
            const float dx = a[u].x - b[u].x;
            const float dy = a[u].y - b[u].y;
            const float dz = a[u].z - b[u].z;
            const float dw = a[u].w - b[u].w;
            s[u] = dx * dx + dy * dy + dz * dz + dw * dw;
        }
        // 4 independent shuffle chains (ILP hides the 26-cyc SHFL latency).
        #pragma unroll
        for (int off = 16; off > 0; off >>= 1) {
            #pragma unroll
            for (int u = 0; u < UNROLL; u++)
                s[u] += __shfl_xor_sync(0xffffffffu, s[u], off);
        }
        if (lane == 0) {
            #pragma unroll
            for (int u = 0; u < UNROLL; u++) {
                const float d = desire[row + u];   // sequential: L1 sector hits
                l_des += (double)d;
                if (s[u] > margin_sq) {
                    l_cnt += 1u;
                    l_inter += (double)d;
                }
            }
        }
    }
    // Remainder rows.
    for (; row < row1; row++) {
        const long base = (long)row * 32 + lane;
        const float4 a = __ldcs(o1 + base);
        const float4 b = __ldcs(o2 + base);
        const float dx = a.x - b.x, dy = a.y - b.y;
        const float dz = a.z - b.z, dw = a.w - b.w;
        float s = dx * dx + dy * dy + dz * dz + dw * dw;
        #pragma unroll
        for (int off = 16; off > 0; off >>= 1)
            s += __shfl_xor_sync(0xffffffffu, s, off);
        if (lane == 0) {
            const float d = desire[row];
            l_des += (double)d;
            if (s > margin_sq) { l_cnt += 1u; l_inter += (double)d; }
        }
    }

    // Block reduction across warps (lane-0 values only).
    __shared__ double       s_inter[8];
    __shared__ double       s_des[8];
    __shared__ unsigned int s_cnt[8];
    __shared__ bool         s_last;
    if (lane == 0) {
        s_inter[warp_in_block] = l_inter;
        s_des[warp_in_block]   = l_des;
        s_cnt[warp_in_block]   = l_cnt;
    }
    __syncthreads();

    if (threadIdx.x == 0) {
        double       bi = 0.0, bd = 0.0;
        unsigned int bc = 0u;
        for (int w = 0; w < warps_per_blk; w++) {
            bi += s_inter[w];
            bd += s_des[w];
            bc += s_cnt[w];
        }
        atomicAdd(&g_inter, bi);
        atomicAdd(&g_desire_sum, bd);
        atomicAdd(&g_count, (unsigned long long)bc);
        __threadfence();
        const unsigned int t = atomicAdd(&g_ticket, 1u);
        s_last = (t == gridDim.x - 1);
    }
    __syncthreads();

    // Last block: compute final scalar, then reset state for the next replay.
    if (s_last && threadIdx.x == 0) {
        __threadfence();
        const double inter = atomicAdd(&g_inter, 0.0);
        const double des   = atomicAdd(&g_desire_sum, 0.0);
        const double cnt   = (double)atomicAdd(&g_count, 0ull);
        const double uni   = cnt + des - inter;
        out[0] = (float)((inter + 1e-6) / (uni + 1e-6));
        g_inter = 0.0;
        g_desire_sum = 0.0;
        g_count = 0ull;
        __threadfence();
        g_ticket = 0u;
    }
}

extern "C" void kernel_launch(void* const* d_in, const int* in_sizes, int n_in,
                              void* d_out, int out_size) {
    const float4* o1     = (const float4*)d_in[0];
    const float4* o2     = (const float4*)d_in[1];
    const float*  desire = (const float*)d_in[2];
    float*        out    = (float*)d_out;

    const int n_rows = in_sizes[2];  // N = 262144

    // 512 blocks x 8 warps = 4096 warps -> 64 contiguous rows/warp.
    // 512 blocks <= 148 SMs x 4 blocks -> single wave, no tail imbalance.
    fra_fused_kernel<<<512, 256>>>(o1, o2, desire, out, n_rows);
}

// round 8
// speedup vs baseline: 1.5262x; 1.5262x over previous
#include <cuda_runtime.h>

// Accumulators in __device__ globals (allocation-free scratch). Read AND reset
// by the last block each launch -> state invariant across graph replays.
__device__ double g_inter = 0.0;
__device__ double g_desire_sum = 0.0;
__device__ unsigned long long g_count = 0ull;
__device__ unsigned int g_ticket = 0u;

// Quarter-warp per row: 8 lanes x 4 float4 = one 128-float row.
// A warp processes a 4-row tile per iteration: 8 LDG.128/thread, then a
// single 3-deep shuffle chain reduces all 4 rows at once.
// Explicit double-buffering: next tile's loads issue BEFORE this tile's
// compute+shuffle, so the warp always has memory in flight.
__global__ __launch_bounds__(256)
void fra_fused_kernel(const float4* __restrict__ o1,
                      const float4* __restrict__ o2,
                      const float*  __restrict__ desire,
                      float* __restrict__ out,
                      int n_rows) {
    const int lane = threadIdx.x & 31;
    const int wib  = threadIdx.x >> 5;
    const int wpb  = blockDim.x >> 5;
    const int wg   = blockIdx.x * wpb + wib;
    const int tw   = gridDim.x * wpb;

    const int g = lane >> 3;   // which row of the 4-row tile (0..3)
    const int j = lane & 7;    // float4 slot within row: covers j, j+8, j+16, j+24

    double       l_inter = 0.0, l_des = 0.0;
    unsigned int l_cnt = 0u;
    const float margin_sq = 0.390625f;   // (1.25/2)^2

    const int n_tiles = n_rows >> 2;

    float4 a0, a1, a2, a3, b0, b1, b2, b3;
    int tile = wg;
    if (tile < n_tiles) {
        const int base = (tile * 4 + g) * 32 + j;
        a0 = o1[base];      b0 = o2[base];
        a1 = o1[base + 8];  b1 = o2[base + 8];
        a2 = o1[base + 16]; b2 = o2[base + 16];
        a3 = o1[base + 24]; b3 = o2[base + 24];
    }

    while (tile < n_tiles) {
        const int next = tile + tw;
        float4 na0, na1, na2, na3, nb0, nb1, nb2, nb3;
        if (next < n_tiles) {          // prefetch next tile FIRST
            const int nb = (next * 4 + g) * 32 + j;
            na0 = o1[nb];      nb0 = o2[nb];
            na1 = o1[nb + 8];  nb1 = o2[nb + 8];
            na2 = o1[nb + 16]; nb2 = o2[nb + 16];
            na3 = o1[nb + 24]; nb3 = o2[nb + 24];
        }

        // 16 squared diffs, two independent FMA chains.
        float s0, s1, d;
        d = a0.x - b0.x; s0  = d * d;   d = a0.y - b0.y; s1  = d * d;
        d = a0.z - b0.z; s0 += d * d;   d = a0.w - b0.w; s1 += d * d;
        d = a1.x - b1.x; s0 += d * d;   d = a1.y - b1.y; s1 += d * d;
        d = a1.z - b1.z; s0 += d * d;   d = a1.w - b1.w; s1 += d * d;
        d = a2.x - b2.x; s0 += d * d;   d = a2.y - b2.y; s1 += d * d;
        d = a2.z - b2.z; s0 += d * d;   d = a2.w - b2.w; s1 += d * d;
        d = a3.x - b3.x; s0 += d * d;   d = a3.y - b3.y; s1 += d * d;
        d = a3.z - b3.z; s0 += d * d;   d = a3.w - b3.w; s1 += d * d;
        float s = s0 + s1;

        // One 3-deep chain reduces within each 8-lane group = all 4 rows.
        s += __shfl_xor_sync(0xffffffffu, s, 4);
        s += __shfl_xor_sync(0xffffffffu, s, 2);
        s += __shfl_xor_sync(0xffffffffu, s, 1);

        if (j == 0) {                  // lanes 0,8,16,24 own rows tile*4+g
            const float dsr = desire[tile * 4 + g];
            l_des += (double)dsr;
            if (s > margin_sq) { l_cnt += 1u; l_inter += (double)dsr; }
        }

        a0 = na0; a1 = na1; a2 = na2; a3 = na3;
        b0 = nb0; b1 = nb1; b2 = nb2; b3 = nb3;
        tile = next;
    }

    // Tail rows (n_rows % 4), handled by warp 0 only.
    if (wg == 0) {
        for (int row = n_tiles * 4; row < n_rows; row++) {
            float s = 0.0f;
            if (g == 0) {
                const int base = row * 32 + j;
                #pragma unroll
                for (int k = 0; k < 4; k++) {
                    const float4 a = o1[base + 8 * k];
                    const float4 b = o2[base + 8 * k];
                    const float dx = a.x - b.x, dy = a.y - b.y;
                    const float dz = a.z - b.z, dw = a.w - b.w;
                    s += dx * dx + dy * dy + dz * dz + dw * dw;
                }
            }
            s += __shfl_xor_sync(0xffffffffu, s, 4);
            s += __shfl_xor_sync(0xffffffffu, s, 2);
            s += __shfl_xor_sync(0xffffffffu, s, 1);
            if (lane == 0) {
                const float dsr = desire[row];
                l_des += (double)dsr;
                if (s > margin_sq) { l_cnt += 1u; l_inter += (double)dsr; }
            }
        }
    }

    // Warp reduction (accumulators live on the j==0 lanes; reduce all 32).
    #pragma unroll
    for (int off = 16; off > 0; off >>= 1) {
        l_inter += __shfl_xor_sync(0xffffffffu, l_inter, off);
        l_des   += __shfl_xor_sync(0xffffffffu, l_des,   off);
        l_cnt   += __shfl_xor_sync(0xffffffffu, l_cnt,   off);
    }

    __shared__ double       s_i[8], s_d[8];
    __shared__ unsigned int s_c[8];
    __shared__ bool         s_last;
    if (lane == 0) { s_i[wib] = l_inter; s_d[wib] = l_des; s_c[wib] = l_cnt; }
    __syncthreads();

    if (threadIdx.x == 0) {
        double       bi = 0.0, bd = 0.0;
        unsigned int bc = 0u;
        for (int w = 0; w < wpb; w++) { bi += s_i[w]; bd += s_d[w]; bc += s_c[w]; }
        atomicAdd(&g_inter, bi);
        atomicAdd(&g_desire_sum, bd);
        atomicAdd(&g_count, (unsigned long long)bc);
        __threadfence();
        s_last = (atomicAdd(&g_ticket, 1u) == gridDim.x - 1);
    }
    __syncthreads();

    if (s_last && threadIdx.x == 0) {
        __threadfence();
        const double inter = atomicAdd(&g_inter, 0.0);
        const double des   = atomicAdd(&g_desire_sum, 0.0);
        const double cnt   = (double)atomicAdd(&g_count, 0ull);
        const double uni   = cnt + des - inter;
        out[0] = (float)((inter + 1e-6) / (uni + 1e-6));
        g_inter = 0.0;
        g_desire_sum = 0.0;
        g_count = 0ull;
        __threadfence();
        g_ticket = 0u;
    }
}

extern "C" void kernel_launch(void* const* d_in, const int* in_sizes, int n_in,
                              void* d_out, int out_size) {
    const float4* o1     = (const float4*)d_in[0];
    const float4* o2     = (const float4*)d_in[1];
    const float*  desire = (const float*)d_in[2];
    float*        out    = (float*)d_out;

    const int n_rows = in_sizes[2];   // N = 262144

    // 296 = 148 SMs x 2 blocks (expected residency at ~90 regs/thread):
    // exactly one wave, grid-strided 4-row tiles for balance.
    fra_fused_kernel<<<296, 256>>>(o1, o2, desire, out, n_rows);
}